// round 11
// baseline (speedup 1.0000x reference)
#include <cuda_runtime.h>
#include <math.h>
#include <stdint.h>

#define B_  128
#define T_  1024
#define NX_ 256
#define NH_ 512
#define NY_ 256

// Progress flags: g_flag[bt][group][jt], row padded to 32 words (128B).
__device__ unsigned g_flag[8][2][32];

// ---------------------------------------------------------------------------
// Generic NT SGEMM (proven): C[m][n] = sum_k A[m][k] * B[n][k]
// ---------------------------------------------------------------------------
template <int BM, int BN, int BK, int TM, int TN, int NT>
__global__ __launch_bounds__(NT) void sgemm_nt(
    const float* __restrict__ A,
    const float* __restrict__ Bm,
    float* __restrict__ C,
    int M, int N, int K)
{
    __shared__ float As[BK][BM];
    __shared__ float Bs[BK][BN];

    const int tid = threadIdx.x;
    const int m0 = blockIdx.y * BM;
    const int n0 = blockIdx.x * BN;
    const int tx = tid % (BN / TN);
    const int ty = tid / (BN / TN);

    float acc[TM][TN];
#pragma unroll
    for (int i = 0; i < TM; i++)
#pragma unroll
        for (int j = 0; j < TN; j++) acc[i][j] = 0.0f;

    for (int k0 = 0; k0 < K; k0 += BK) {
#pragma unroll
        for (int i = tid; i < BM * (BK / 4); i += NT) {
            int m = i / (BK / 4);
            int kq = (i % (BK / 4)) * 4;
            float4 v = *(const float4*)(A + (long)(m0 + m) * K + k0 + kq);
            As[kq + 0][m] = v.x;
            As[kq + 1][m] = v.y;
            As[kq + 2][m] = v.z;
            As[kq + 3][m] = v.w;
        }
#pragma unroll
        for (int i = tid; i < BN * (BK / 4); i += NT) {
            int n = i / (BK / 4);
            int kq = (i % (BK / 4)) * 4;
            float4 v = *(const float4*)(Bm + (long)(n0 + n) * K + k0 + kq);
            Bs[kq + 0][n] = v.x;
            Bs[kq + 1][n] = v.y;
            Bs[kq + 2][n] = v.z;
            Bs[kq + 3][n] = v.w;
        }
        __syncthreads();

#pragma unroll
        for (int k = 0; k < BK; ++k) {
            float a[TM], b[TN];
#pragma unroll
            for (int i = 0; i < TM; i++) a[i] = As[k][ty * TM + i];
#pragma unroll
            for (int j = 0; j < TN; j++) b[j] = Bs[k][tx * TN + j];
#pragma unroll
            for (int i = 0; i < TM; i++)
#pragma unroll
                for (int j = 0; j < TN; j++) acc[i][j] = fmaf(a[i], b[j], acc[i][j]);
        }
        __syncthreads();
    }

#pragma unroll
    for (int i = 0; i < TM; i++) {
        float4 v = make_float4(acc[i][0], acc[i][1], acc[i][2], acc[i][3]);
        *(float4*)(C + (long)(m0 + ty * TM + i) * N + n0 + tx * TN) = v;
    }
}

// ---------------------------------------------------------------------------
// Helpers
// ---------------------------------------------------------------------------
__device__ __forceinline__ void ffma2(unsigned long long& d,
                                      unsigned long long a, unsigned long long b)
{
    asm("fma.rn.f32x2 %0, %1, %2, %0;" : "+l"(d) : "l"(a), "l"(b));
}
__device__ __forceinline__ void unpack2(unsigned long long v, float& lo, float& hi)
{
    asm("mov.b64 {%0, %1}, %2;" : "=f"(lo), "=f"(hi) : "l"(v));
}
__device__ __forceinline__ unsigned ld_acq(const unsigned* p)
{
    unsigned v;
    asm volatile("ld.global.acquire.gpu.u32 %0, [%1];" : "=r"(v) : "l"(p) : "memory");
    return v;
}
__device__ __forceinline__ void st_rel(unsigned* p, unsigned v)
{
    asm volatile("st.global.release.gpu.u32 [%0], %1;" :: "l"(p), "r"(v) : "memory");
}
__device__ __forceinline__ void bar_named(int id)
{
    asm volatile("bar.sync %0, 256;" :: "r"(id) : "memory");
}

// ---------------------------------------------------------------------------
// Sequential recurrence v6: SPATIAL group overlap on the lean data path.
//
// Grid = 128 CTAs = 8 bt x 16 jt. 512 threads = 2 groups x 8 warps.
// CTA owns 16 batches x 32 cols; group g = warps g*8..+8 handles batches
// bt*16 + g*8..+8 (fully independent: own flags, own named barrier, own red).
// Per group: 8-warp k-split(64); lane owns 1 col; W = 32 u64 regs resident.
// Warp-private hTw reload; u64 partials; tolerance-window flag poll.
// While group X stalls (poll/fence/reduce), group Y's warps issue FMAs.
// SMEM: hTw[16w][8b][68] 34.8KB + red[2g][8w][8b][32j] u64 32KB = 66.6KB.
// ---------------------------------------------------------------------------
#define NTHR     512
#define HTW_STR  (8 * 68)                    // 544 floats per warp
#define RED_FOFF (16 * HTW_STR)              // 8704 floats
#define SMEM_BYTES (RED_FOFF * 4 + 2 * 2048 * 8)   // 34816 + 32768 = 67584

__global__ __launch_bounds__(NTHR, 1) void rnn_seq6(
    const float* __restrict__ Wh,   // [NH][NH]
    const float* __restrict__ h0,   // [B][NH]
    float* __restrict__ hs)         // [B][T][NH]: pre in, h out (in place)
{
    extern __shared__ float sm[];

    const int tid  = threadIdx.x;
    const int wid  = tid >> 5;
    const int lane = tid & 31;
    const int gid  = wid >> 3;          // group 0/1
    const int widg = wid & 7;           // warp within group
    const int tidg = tid & 255;         // thread within group

    const int jt  = blockIdx.x & 15;
    const int bt  = blockIdx.x >> 4;
    const int j0g = jt * 32;
    const int b0g = bt * 16 + gid * 8;  // this group's 8 batches
    const int kw0 = widg * 64;

    float* hTw = sm + wid * HTW_STR;                                  // [8][68]
    unsigned long long* red =
        (unsigned long long*)(sm + RED_FOFF) + (size_t)gid * 2048;   // [8][8][32]
    unsigned* flags = &g_flag[bt][gid][0];

    // ---- Wh slice into registers: col j0g+lane, k = kw0..kw0+64 ----
    unsigned long long W[32];
    {
        const float* row = Wh + (size_t)(j0g + lane) * NH_ + kw0;
#pragma unroll
        for (int q = 0; q < 16; ++q) {
            ulonglong2 v = *(const ulonglong2*)(row + q * 4);
            W[2 * q]     = v.x;
            W[2 * q + 1] = v.y;
        }
    }

    // reload mapping: lane -> (batch rb = lane>>2, 16-float segment seg)
    const int rb  = lane >> 2;
    const int seg = lane & 3;

    // epilogue mapping: one output per group-thread: b = tidg>>5, j = tidg&31
    const int eb = tidg >> 5;
    const int ej = tidg & 31;

    for (int t = 0; t < T_; ++t) {
        // ---- prefetch this step's pre-activation ----
        float pre = __ldcg(hs + ((size_t)(b0g + eb) * T_ + t) * NH_ + j0g + ej);

        // ---- wait: all 16 peer CTAs published this group's h_{t-1} ----
        if (t > 0) {
            for (;;) {
                unsigned v = (lane < 16) ? ld_acq(flags + lane) : (unsigned)t;
                if (__all_sync(0xffffffffu, (v - (unsigned)t) <= 1u)) break;
                __nanosleep(20);
            }
        }

        // ---- warp-local reload: 8 batches x 64-k slice -> hTw ----
        {
            const float* src = (t == 0)
                ? h0 + (size_t)(b0g + rb) * NH_ + kw0 + seg * 16
                : hs + ((size_t)(b0g + rb) * T_ + (t - 1)) * NH_ + kw0 + seg * 16;
#pragma unroll
            for (int q = 0; q < 4; ++q)
                *(float4*)&hTw[rb * 68 + seg * 16 + q * 4] =
                    __ldcg((const float4*)(src + q * 4));
        }
        __syncwarp();

        // ---- k-loop: 1 col, SIMD along k; 2 FFMA2 per broadcast LDS.128 ----
        unsigned long long acc[8];
#pragma unroll
        for (int b = 0; b < 8; ++b) acc[b] = 0ull;

#pragma unroll
        for (int b = 0; b < 8; ++b) {
            const float* hb = &hTw[b * 68];
#pragma unroll
            for (int q = 0; q < 16; ++q) {
                ulonglong2 va = *(const ulonglong2*)(hb + q * 4);   // broadcast
                ffma2(acc[b], va.x, W[2 * q]);
                ffma2(acc[b], va.y, W[2 * q + 1]);
            }
        }

        // ---- stash partials: red[widg][b][lane] u64 ----
#pragma unroll
        for (int b = 0; b < 8; ++b)
            red[(size_t)(widg * 8 + b) * 32 + lane] = acc[b];
        bar_named(gid + 1);

        // ---- reduce 8 warps, fold k-pairs, add pre, tanh, publish h ----
        {
            float s = pre;
#pragma unroll
            for (int w = 0; w < 8; ++w) {
                float lo, hi;
                unpack2(red[(size_t)(w * 8 + eb) * 32 + ej], lo, hi);
                s += lo + hi;
            }
            float hv = tanhf(s);
            hs[((size_t)(b0g + eb) * T_ + t) * NH_ + j0g + ej] = hv;
        }

        // ---- fence, group join, release group flag ----
        __threadfence();
        bar_named(gid + 1);
        if (tidg == 0) st_rel(flags + jt, (unsigned)(t + 1));
    }
}

// ---------------------------------------------------------------------------
// Launch: [sgemm(pre), rnn_seq6, sgemm(y)]
// ---------------------------------------------------------------------------
extern "C" void kernel_launch(void* const* d_in, const int* in_sizes, int n_in,
                              void* d_out, int out_size)
{
    const float* x  = (const float*)d_in[0];
    const float* h0 = (const float*)d_in[1];
    const float* Wi = (const float*)d_in[2];
    const float* Wh = (const float*)d_in[3];
    const float* Wy = (const float*)d_in[4];

    float* y  = (float*)d_out;
    float* hs = y + (size_t)B_ * T_ * NY_;

    // Phase 1: pre = x @ Wi^T -> hs region (scratch)
    {
        dim3 grid(NH_ / 64, (B_ * T_) / 128);
        sgemm_nt<128, 64, 16, 8, 4, 256><<<grid, 256>>>(x, Wi, hs, B_ * T_, NH_, NX_);
    }
    // Phase 2: sequential recurrence (spatial group overlap)
    {
        cudaFuncSetAttribute(rnn_seq6,
                             cudaFuncAttributeMaxDynamicSharedMemorySize, SMEM_BYTES);
        rnn_seq6<<<128, NTHR, SMEM_BYTES>>>(Wh, h0, hs);
    }
    // Phase 3: y = hs @ Wy^T
    {
        dim3 grid(NY_ / 64, (B_ * T_) / 128);
        sgemm_nt<128, 64, 16, 8, 4, 256><<<grid, 256>>>(hs, Wy, y, B_ * T_, NY_, NH_);
    }
}

// round 12
// speedup vs baseline: 1.8267x; 1.8267x over previous
#include <cuda_runtime.h>
#include <math.h>
#include <stdint.h>

#define B_  128
#define T_  1024
#define NX_ 256
#define NH_ 512
#define NY_ 256

// Progress flags: g_flag2[bt][group][jt], row padded to 32 words (128B).
__device__ unsigned g_flag2[16][2][32];

// ---------------------------------------------------------------------------
// FFMA2 helpers
// ---------------------------------------------------------------------------
__device__ __forceinline__ void ffma2(unsigned long long& d,
                                      unsigned long long a, unsigned long long b)
{
    asm("fma.rn.f32x2 %0, %1, %2, %0;" : "+l"(d) : "l"(a), "l"(b));
}
__device__ __forceinline__ unsigned long long pack2(float x)
{
    unsigned long long r;
    asm("mov.b64 %0, {%1, %1};" : "=l"(r) : "f"(x));
    return r;
}
__device__ __forceinline__ void unpack2(unsigned long long v, float& lo, float& hi)
{
    asm("mov.b64 {%0, %1}, %2;" : "=f"(lo), "=f"(hi) : "l"(v));
}
__device__ __forceinline__ unsigned ld_acq(const unsigned* p)
{
    unsigned v;
    asm volatile("ld.global.acquire.gpu.u32 %0, [%1];" : "=r"(v) : "l"(p) : "memory");
    return v;
}
__device__ __forceinline__ void st_rel(unsigned* p, unsigned v)
{
    asm volatile("st.global.release.gpu.u32 [%0], %1;" :: "l"(p), "r"(v) : "memory");
}

// ---------------------------------------------------------------------------
// FFMA2 NT SGEMM: C[m][n] = sum_k A[m][k] * B[n][k]
// 128x128 tile, BK=16, 256 threads, thread tile 8x8 (4 packed col-pairs).
// ---------------------------------------------------------------------------
__global__ __launch_bounds__(256) void sgemm_nt2(
    const float* __restrict__ A,
    const float* __restrict__ Bm,
    float* __restrict__ C,
    int M, int N, int K)
{
    __shared__ float As[16][128];
    __shared__ float Bs[16][128];

    const int tid = threadIdx.x;
    const int m0 = blockIdx.y * 128;
    const int n0 = blockIdx.x * 128;
    const int tx = tid & 15;        // n-group: cols tx*8..+8
    const int ty = tid >> 4;        // m-group: rows ty*8..+8

    unsigned long long acc[8][4];
#pragma unroll
    for (int i = 0; i < 8; i++)
#pragma unroll
        for (int j = 0; j < 4; j++) acc[i][j] = 0ull;

    for (int k0 = 0; k0 < K; k0 += 16) {
        // A tile: 128 rows x 16 k -> As[k][m]
#pragma unroll
        for (int q = 0; q < 2; ++q) {
            int i = tid + q * 256;          // 0..511
            int m = i >> 2;
            int kq = (i & 3) * 4;
            float4 v = *(const float4*)(A + (long)(m0 + m) * K + k0 + kq);
            As[kq + 0][m] = v.x;
            As[kq + 1][m] = v.y;
            As[kq + 2][m] = v.z;
            As[kq + 3][m] = v.w;
        }
        // B tile: 128 rows(n) x 16 k -> Bs[k][n]
#pragma unroll
        for (int q = 0; q < 2; ++q) {
            int i = tid + q * 256;
            int n = i >> 2;
            int kq = (i & 3) * 4;
            float4 v = *(const float4*)(Bm + (long)(n0 + n) * K + k0 + kq);
            Bs[kq + 0][n] = v.x;
            Bs[kq + 1][n] = v.y;
            Bs[kq + 2][n] = v.z;
            Bs[kq + 3][n] = v.w;
        }
        __syncthreads();

#pragma unroll
        for (int k = 0; k < 16; ++k) {
            float a[8];
#pragma unroll
            for (int q = 0; q < 2; ++q)
                *(float4*)&a[q * 4] = *(const float4*)&As[k][ty * 8 + q * 4];
            ulonglong2 b01 = *(const ulonglong2*)&Bs[k][tx * 8];
            ulonglong2 b23 = *(const ulonglong2*)&Bs[k][tx * 8 + 4];
#pragma unroll
            for (int i = 0; i < 8; ++i) {
                unsigned long long ai = pack2(a[i]);
                ffma2(acc[i][0], ai, b01.x);
                ffma2(acc[i][1], ai, b01.y);
                ffma2(acc[i][2], ai, b23.x);
                ffma2(acc[i][3], ai, b23.y);
            }
        }
        __syncthreads();
    }

#pragma unroll
    for (int i = 0; i < 8; ++i) {
        float r[8];
#pragma unroll
        for (int j = 0; j < 4; ++j) unpack2(acc[i][j], r[2 * j], r[2 * j + 1]);
        float* dst = C + (long)(m0 + ty * 8 + i) * N + n0 + tx * 8;
        *(float4*)dst       = *(float4*)&r[0];
        *(float4*)(dst + 4) = *(float4*)&r[4];
    }
}

// ---------------------------------------------------------------------------
// Sequential recurrence v7 = R10 (temporal 2-group phase shift) + sparse
// per-warp dependencies: warp widg polls ONLY CTA widg's flag (its k-slice
// producer). Mutual pairs bound skew <= 1; window v in {t, t+1} keeps the
// graph-replay ratchet safety.
// Grid = 128 CTAs = 16 bt x 8 jt. 256 threads = 8 warps (k-split 64 each).
// ---------------------------------------------------------------------------
#define NTHR     256
#define HTW_STR  272                       // 4*68 floats per (warp,group)
#define RED_FOFF (16 * HTW_STR)            // 4352 floats
#define SMEM_BYTES (RED_FOFF * 4 + 2 * 2048 * 8)   // 50176

struct GroupCtx {
    unsigned* flags;
    float* hTw;
    unsigned long long* red;
    int b0g;
};

__device__ __forceinline__ void rnn_do_group(
    int t, const GroupCtx& G,
    const float* __restrict__ h0, float* __restrict__ hs,
    const unsigned long long* W, float pre,
    int jt, int j0g, int kw0, int widg,
    int tid, int lane, int wid, int eb, int ej)
{
    // ---- wait: ONLY the producer of this warp's k-slice (CTA widg) ----
    if (t > 0) {
        const unsigned* fp = G.flags + widg;   // all lanes same address: broadcast
        for (;;) {
            unsigned v = ld_acq(fp);
            if ((v - (unsigned)t) <= 1u) break;
            __nanosleep(20);
        }
    }

    // ---- warp-local reload: 4 batches x 64-k slice -> hTw ----
    {
        int rb = lane >> 3;
        int f4 = (lane & 7) * 8;
        const float* src = (t == 0)
            ? h0 + (size_t)(G.b0g + rb) * NH_ + kw0 + f4
            : hs + ((size_t)(G.b0g + rb) * T_ + (t - 1)) * NH_ + kw0 + f4;
        float4 v0 = __ldcg((const float4*)(src));
        float4 v1 = __ldcg((const float4*)(src + 4));
        *(float4*)&G.hTw[rb * 68 + f4]     = v0;
        *(float4*)&G.hTw[rb * 68 + f4 + 4] = v1;
    }
    __syncwarp();

    // ---- k-loop: 4 FFMA2 per broadcast LDS.128 ----
    unsigned long long acc[4][2];
#pragma unroll
    for (int b = 0; b < 4; ++b) { acc[b][0] = 0ull; acc[b][1] = 0ull; }

#pragma unroll
    for (int b = 0; b < 4; ++b) {
        const float* hb = &G.hTw[b * 68];
#pragma unroll
        for (int q = 0; q < 16; ++q) {
            ulonglong2 va = *(const ulonglong2*)(hb + q * 4);
            ffma2(acc[b][0], va.x, W[2 * q]);
            ffma2(acc[b][0], va.y, W[2 * q + 1]);
            ffma2(acc[b][1], va.x, W[32 + 2 * q]);
            ffma2(acc[b][1], va.y, W[32 + 2 * q + 1]);
        }
    }

    // ---- stash partials ----
#pragma unroll
    for (int b = 0; b < 4; ++b) {
        ulonglong2 v; v.x = acc[b][0]; v.y = acc[b][1];
        *(ulonglong2*)&G.red[(size_t)wid * 256 + b * 64 + lane * 2] = v;
    }
    __syncthreads();

    // ---- reduce 8 warps, fold k-pairs, add pre, tanh, publish h ----
    {
        float s = pre;
#pragma unroll
        for (int w = 0; w < 8; ++w) {
            float lo, hi;
            unpack2(G.red[(size_t)w * 256 + eb * 64 + ej], lo, hi);
            s += lo + hi;
        }
        float hv = tanhf(s);
        hs[((size_t)(G.b0g + eb) * T_ + t) * NH_ + j0g + ej] = hv;
    }

    // ---- fence, join, release this CTA's flag ----
    __threadfence();
    __syncthreads();
    if (tid == 0) st_rel(G.flags + jt, (unsigned)(t + 1));
}

__global__ __launch_bounds__(NTHR, 1) void rnn_seq7(
    const float* __restrict__ Wh,
    const float* __restrict__ h0,
    float* __restrict__ hs)
{
    extern __shared__ float sm[];

    const int tid  = threadIdx.x;
    const int wid  = tid >> 5;
    const int lane = tid & 31;

    const int jt  = blockIdx.x & 7;
    const int bt  = blockIdx.x >> 3;
    const int j0g = jt * 64;
    const int b0  = bt * 8;
    const int kw0 = wid * 64;

    // ---- Wh slice into registers (cols lane*2, lane*2+1; k = kw0..+64) ----
    unsigned long long W[64];
#pragma unroll
    for (int c = 0; c < 2; ++c) {
        const float* row = Wh + (size_t)(j0g + lane * 2 + c) * NH_ + kw0;
#pragma unroll
        for (int q = 0; q < 16; ++q) {
            ulonglong2 v = *(const ulonglong2*)(row + q * 4);
            W[c * 32 + 2 * q]     = v.x;
            W[c * 32 + 2 * q + 1] = v.y;
        }
    }

    const int eb = tid >> 6;   // 0..3
    const int ej = tid & 63;

    GroupCtx GA, GB;
    GA.flags = &g_flag2[bt][0][0];
    GB.flags = &g_flag2[bt][1][0];
    GA.hTw   = sm + (wid * 2 + 0) * HTW_STR;
    GB.hTw   = sm + (wid * 2 + 1) * HTW_STR;
    GA.red   = (unsigned long long*)(sm + RED_FOFF);
    GB.red   = GA.red + 2048;
    GA.b0g   = b0;
    GB.b0g   = b0 + 4;

    for (int t = 0; t < T_; ++t) {
        float preA = __ldcg(hs + ((size_t)(b0 + eb) * T_ + t) * NH_ + j0g + ej);
        float preB = __ldcg(hs + ((size_t)(b0 + 4 + eb) * T_ + t) * NH_ + j0g + ej);

        rnn_do_group(t, GA, h0, hs, W, preA, jt, j0g, kw0, wid, tid, lane, wid, eb, ej);
        rnn_do_group(t, GB, h0, hs, W, preB, jt, j0g, kw0, wid, tid, lane, wid, eb, ej);
    }
}

// ---------------------------------------------------------------------------
// Launch: [sgemm2(pre), rnn_seq7, sgemm2(y)]
// ---------------------------------------------------------------------------
extern "C" void kernel_launch(void* const* d_in, const int* in_sizes, int n_in,
                              void* d_out, int out_size)
{
    const float* x  = (const float*)d_in[0];
    const float* h0 = (const float*)d_in[1];
    const float* Wi = (const float*)d_in[2];
    const float* Wh = (const float*)d_in[3];
    const float* Wy = (const float*)d_in[4];

    float* y  = (float*)d_out;
    float* hs = y + (size_t)B_ * T_ * NY_;

    // Phase 1: pre = x @ Wi^T -> hs region (scratch)
    {
        dim3 grid(NH_ / 128, (B_ * T_) / 128);
        sgemm_nt2<<<grid, 256>>>(x, Wi, hs, B_ * T_, NH_, NX_);
    }
    // Phase 2: sequential recurrence (temporal phase shift + sparse deps)
    {
        cudaFuncSetAttribute(rnn_seq7,
                             cudaFuncAttributeMaxDynamicSharedMemorySize, SMEM_BYTES);
        rnn_seq7<<<128, NTHR, SMEM_BYTES>>>(Wh, h0, hs);
    }
    // Phase 3: y = hs @ Wy^T
    {
        dim3 grid(NY_ / 128, (B_ * T_) / 128);
        sgemm_nt2<<<grid, 256>>>(hs, Wy, y, B_ * T_, NY_, NH_);
    }
}

// round 13
// speedup vs baseline: 2.2505x; 1.2320x over previous
#include <cuda_runtime.h>
#include <math.h>
#include <stdint.h>

#define B_  128
#define T_  1024
#define NX_ 256
#define NH_ 512
#define NY_ 256

// Progress flags: g_flag2[bt][group][jt], row padded to 32 words (128B).
__device__ unsigned g_flag2[16][2][32];

// ---------------------------------------------------------------------------
// FFMA2 helpers
// ---------------------------------------------------------------------------
__device__ __forceinline__ void ffma2(unsigned long long& d,
                                      unsigned long long a, unsigned long long b)
{
    asm("fma.rn.f32x2 %0, %1, %2, %0;" : "+l"(d) : "l"(a), "l"(b));
}
__device__ __forceinline__ unsigned long long pack2(float x)
{
    unsigned long long r;
    asm("mov.b64 %0, {%1, %1};" : "=l"(r) : "f"(x));
    return r;
}
__device__ __forceinline__ void unpack2(unsigned long long v, float& lo, float& hi)
{
    asm("mov.b64 {%0, %1}, %2;" : "=f"(lo), "=f"(hi) : "l"(v));
}
__device__ __forceinline__ unsigned ld_acq(const unsigned* p)
{
    unsigned v;
    asm volatile("ld.global.acquire.gpu.u32 %0, [%1];" : "=r"(v) : "l"(p) : "memory");
    return v;
}
__device__ __forceinline__ void st_rel(unsigned* p, unsigned v)
{
    asm volatile("st.global.release.gpu.u32 [%0], %1;" :: "l"(p), "r"(v) : "memory");
}

// ---------------------------------------------------------------------------
// FFMA2 NT SGEMM (proven, R12): C[m][n] = sum_k A[m][k] * B[n][k]
// ---------------------------------------------------------------------------
__global__ __launch_bounds__(256) void sgemm_nt2(
    const float* __restrict__ A,
    const float* __restrict__ Bm,
    float* __restrict__ C,
    int M, int N, int K)
{
    __shared__ float As[16][128];
    __shared__ float Bs[16][128];

    const int tid = threadIdx.x;
    const int m0 = blockIdx.y * 128;
    const int n0 = blockIdx.x * 128;
    const int tx = tid & 15;
    const int ty = tid >> 4;

    unsigned long long acc[8][4];
#pragma unroll
    for (int i = 0; i < 8; i++)
#pragma unroll
        for (int j = 0; j < 4; j++) acc[i][j] = 0ull;

    for (int k0 = 0; k0 < K; k0 += 16) {
#pragma unroll
        for (int q = 0; q < 2; ++q) {
            int i = tid + q * 256;
            int m = i >> 2;
            int kq = (i & 3) * 4;
            float4 v = *(const float4*)(A + (long)(m0 + m) * K + k0 + kq);
            As[kq + 0][m] = v.x;
            As[kq + 1][m] = v.y;
            As[kq + 2][m] = v.z;
            As[kq + 3][m] = v.w;
        }
#pragma unroll
        for (int q = 0; q < 2; ++q) {
            int i = tid + q * 256;
            int n = i >> 2;
            int kq = (i & 3) * 4;
            float4 v = *(const float4*)(Bm + (long)(n0 + n) * K + k0 + kq);
            Bs[kq + 0][n] = v.x;
            Bs[kq + 1][n] = v.y;
            Bs[kq + 2][n] = v.z;
            Bs[kq + 3][n] = v.w;
        }
        __syncthreads();

#pragma unroll
        for (int k = 0; k < 16; ++k) {
            float a[8];
#pragma unroll
            for (int q = 0; q < 2; ++q)
                *(float4*)&a[q * 4] = *(const float4*)&As[k][ty * 8 + q * 4];
            ulonglong2 b01 = *(const ulonglong2*)&Bs[k][tx * 8];
            ulonglong2 b23 = *(const ulonglong2*)&Bs[k][tx * 8 + 4];
#pragma unroll
            for (int i = 0; i < 8; ++i) {
                unsigned long long ai = pack2(a[i]);
                ffma2(acc[i][0], ai, b01.x);
                ffma2(acc[i][1], ai, b01.y);
                ffma2(acc[i][2], ai, b23.x);
                ffma2(acc[i][3], ai, b23.y);
            }
        }
        __syncthreads();
    }

#pragma unroll
    for (int i = 0; i < 8; ++i) {
        float r[8];
#pragma unroll
        for (int j = 0; j < 4; ++j) unpack2(acc[i][j], r[2 * j], r[2 * j + 1]);
        float* dst = C + (long)(m0 + ty * 8 + i) * N + n0 + tx * 8;
        *(float4*)dst       = *(float4*)&r[0];
        *(float4*)(dst + 4) = *(float4*)&r[4];
    }
}

// ---------------------------------------------------------------------------
// Sequential recurrence v8: R12 + software-pipelined phase boundary.
//
// Grid = 128 CTAs = 16 bt x 8 jt. 256 threads = 8 warps (k-split 64 each).
// Temporal 2-group phase shift (groups of 4 batches). Per phase:
//   STS prefetched h (regs) -> hTw; kloop; SPECULATIVE acquire + LDG of the
//   next phase's h (drains under reduce/publish); reduce+tanh+STG;
//   st.release flag (no threadfence — release + bar.sync provide ordering);
//   retry-reload only if the speculative flag read was stale.
// Sparse per-warp deps: warp wid polls only CTA wid's flag (its k-slice
// producer); window (v - t) <= 1 preserves skew bound + replay safety.
// ---------------------------------------------------------------------------
#define NTHR     256
#define HTW_STR  272                       // 4*68 floats per (warp,group)
#define RED_FOFF (16 * HTW_STR)            // 4352 floats
#define SMEM_BYTES (RED_FOFF * 4 + 2 * 2048 * 8)   // 50176

__global__ __launch_bounds__(NTHR, 1) void rnn_seq8(
    const float* __restrict__ Wh,   // [NH][NH]
    const float* __restrict__ h0,   // [B][NH]
    float* __restrict__ hs)         // [B][T][NH]: pre in, h out (in place)
{
    extern __shared__ float sm[];

    const int tid  = threadIdx.x;
    const int wid  = tid >> 5;
    const int lane = tid & 31;

    const int jt  = blockIdx.x & 7;
    const int bt  = blockIdx.x >> 3;
    const int j0g = jt * 64;
    const int b0  = bt * 8;
    const int kw0 = wid * 64;

    // ---- Wh slice into registers (cols lane*2, lane*2+1; k = kw0..+64) ----
    unsigned long long W[64];
#pragma unroll
    for (int c = 0; c < 2; ++c) {
        const float* row = Wh + (size_t)(j0g + lane * 2 + c) * NH_ + kw0;
#pragma unroll
        for (int q = 0; q < 16; ++q) {
            ulonglong2 v = *(const ulonglong2*)(row + q * 4);
            W[c * 32 + 2 * q]     = v.x;
            W[c * 32 + 2 * q + 1] = v.y;
        }
    }

    // reload mapping: lane -> (batch rb, 8-float chunk f4)
    const int rb = lane >> 3;
    const int f4 = (lane & 7) * 8;
    // epilogue mapping
    const int eb = tid >> 6;   // 0..3
    const int ej = tid & 63;

    // ---- prologue: prefetch phase 0 (g=0, t=0) h from h0 ----
    float4 hx0, hx1;
    {
        const float* src = h0 + (size_t)(b0 + rb) * NH_ + kw0 + f4;
        hx0 = __ldcg((const float4*)src);
        hx1 = __ldcg((const float4*)(src + 4));
    }

    for (int p = 0; p < 2 * T_; ++p) {
        const int g = p & 1;
        const int t = p >> 1;
        unsigned* flags = &g_flag2[bt][g][0];
        float* hTw = sm + (wid * 2 + g) * HTW_STR;
        unsigned long long* red =
            (unsigned long long*)(sm + RED_FOFF) + (size_t)g * 2048;
        const int b0g = b0 + g * 4;

        // pre-activation for this phase (consumed at reduce)
        float pre = __ldcg(hs + ((size_t)(b0g + eb) * T_ + t) * NH_ + j0g + ej);

        // ---- STS prefetched h, then k-loop ----
        *(float4*)&hTw[rb * 68 + f4]     = hx0;
        *(float4*)&hTw[rb * 68 + f4 + 4] = hx1;
        __syncwarp();

        unsigned long long acc[4][2];
#pragma unroll
        for (int b = 0; b < 4; ++b) { acc[b][0] = 0ull; acc[b][1] = 0ull; }

#pragma unroll
        for (int b = 0; b < 4; ++b) {
            const float* hb = &hTw[b * 68];
#pragma unroll
            for (int q = 0; q < 16; ++q) {
                ulonglong2 va = *(const ulonglong2*)(hb + q * 4);
                ffma2(acc[b][0], va.x, W[2 * q]);
                ffma2(acc[b][0], va.y, W[2 * q + 1]);
                ffma2(acc[b][1], va.x, W[32 + 2 * q]);
                ffma2(acc[b][1], va.y, W[32 + 2 * q + 1]);
            }
        }

        // ---- speculative next-phase prefetch (drains under reduce/publish) --
        const unsigned* f2p = nullptr;
        const float* nsrc = nullptr;
        unsigned vflag = 0;
        int t2 = 0;
        if (p + 1 < 2 * T_) {
            const int g2 = g ^ 1;
            t2 = (p + 1) >> 1;
            const int b0g2 = b0 + g2 * 4;
            if (t2 == 0) {
                nsrc = h0 + (size_t)(b0g2 + rb) * NH_ + kw0 + f4;
            } else {
                f2p = &g_flag2[bt][g2][0] + wid;
                vflag = ld_acq(f2p);   // acquire orders the ldcg's below
                nsrc = hs + ((size_t)(b0g2 + rb) * T_ + (t2 - 1)) * NH_ + kw0 + f4;
            }
            hx0 = __ldcg((const float4*)nsrc);
            hx1 = __ldcg((const float4*)(nsrc + 4));
        }

        // ---- stash partials, reduce, tanh, publish ----
#pragma unroll
        for (int b = 0; b < 4; ++b) {
            ulonglong2 v; v.x = acc[b][0]; v.y = acc[b][1];
            *(ulonglong2*)&red[(size_t)wid * 256 + b * 64 + lane * 2] = v;
        }
        __syncthreads();

        {
            float s = pre;
#pragma unroll
            for (int w = 0; w < 8; ++w) {
                float lo, hi;
                unpack2(red[(size_t)w * 256 + eb * 64 + ej], lo, hi);
                s += lo + hi;
            }
            float hv = tanhf(s);
            hs[((size_t)(b0g + eb) * T_ + t) * NH_ + j0g + ej] = hv;
        }

        __syncthreads();
        if (tid == 0) st_rel(flags + jt, (unsigned)(t + 1));

        // ---- retry slow path: speculative read was stale ----
        if (f2p != nullptr && (vflag - (unsigned)t2) > 1u) {
            for (;;) {
                unsigned v = ld_acq(f2p);
                if ((v - (unsigned)t2) <= 1u) break;
                __nanosleep(20);
            }
            hx0 = __ldcg((const float4*)nsrc);
            hx1 = __ldcg((const float4*)(nsrc + 4));
        }
    }
}

// ---------------------------------------------------------------------------
// Launch: [sgemm2(pre), rnn_seq8, sgemm2(y)]
// ---------------------------------------------------------------------------
extern "C" void kernel_launch(void* const* d_in, const int* in_sizes, int n_in,
                              void* d_out, int out_size)
{
    const float* x  = (const float*)d_in[0];
    const float* h0 = (const float*)d_in[1];
    const float* Wi = (const float*)d_in[2];
    const float* Wh = (const float*)d_in[3];
    const float* Wy = (const float*)d_in[4];

    float* y  = (float*)d_out;
    float* hs = y + (size_t)B_ * T_ * NY_;

    // Phase 1: pre = x @ Wi^T -> hs region (scratch)
    {
        dim3 grid(NH_ / 128, (B_ * T_) / 128);
        sgemm_nt2<<<grid, 256>>>(x, Wi, hs, B_ * T_, NH_, NX_);
    }
    // Phase 2: sequential recurrence (pipelined phase boundary)
    {
        cudaFuncSetAttribute(rnn_seq8,
                             cudaFuncAttributeMaxDynamicSharedMemorySize, SMEM_BYTES);
        rnn_seq8<<<128, NTHR, SMEM_BYTES>>>(Wh, h0, hs);
    }
    // Phase 3: y = hs @ Wy^T
    {
        dim3 grid(NY_ / 128, (B_ * T_) / 128);
        sgemm_nt2<<<grid, 256>>>(hs, Wy, y, B_ * T_, NY_, NH_);
    }
}